// round 4
// baseline (speedup 1.0000x reference)
#include <cuda_runtime.h>
#include <cuda_bf16.h>

#define EPSF 1e-10f

// Persistent scratch (no allocations allowed). Reset by the last block each
// run, so every graph replay starts from a clean state.
__device__ double g_acc = 0.0;
__device__ unsigned int g_done = 0;

__device__ __forceinline__ float elem_term(float p, int y, float lam) {
    // y==0 -> -log(1 - p + eps); else -> -lam * log(p + eps)
    bool neg = (y == 0);
    float arg   = neg ? (1.0f - p + EPSF) : (p + EPSF);
    float scale = neg ? 1.0f : lam;
    return -scale * __logf(arg);
}

__global__ void __launch_bounds__(256, 8)
sparse_loss_fused(const float* __restrict__ pred,
                  const int* __restrict__ y,
                  const int* __restrict__ lamda_raw,
                  float* __restrict__ out,
                  int n, int per_block) {
    // Disambiguate lamda dtype: small non-negative int bit-pattern -> integer,
    // otherwise reinterpret bits as float. (int 5 and float 5.0f both -> 5.0f)
    int ibits = *lamda_raw;
    float lam = (ibits >= 0 && ibits < 1000000) ? (float)ibits : __int_as_float(ibits);

    int nvec = n >> 2;  // float4 count
    const float4* __restrict__ p4 = (const float4*)pred;
    const int4*   __restrict__ y4 = (const int4*)y;

    // Blocked-contiguous: each CTA owns one contiguous slice of the arrays so
    // every SM streams linearly through memory (max page/row locality).
    int beg = blockIdx.x * per_block;
    int end = beg + per_block;
    if (end > nvec) end = nvec;

    float acc = 0.0f;
    const int bs = 256;  // blockDim.x

    int i = beg + threadIdx.x;
    // 2-deep software pipeline within the contiguous slice (4 LDG.128 in flight)
    for (; i + bs < end; i += 2 * bs) {
        float4 p0 = __ldcs(p4 + i);
        float4 p1 = __ldcs(p4 + i + bs);
        int4   t0 = __ldcs(y4 + i);
        int4   t1 = __ldcs(y4 + i + bs);
        acc += elem_term(p0.x, t0.x, lam) + elem_term(p0.y, t0.y, lam)
             + elem_term(p0.z, t0.z, lam) + elem_term(p0.w, t0.w, lam);
        acc += elem_term(p1.x, t1.x, lam) + elem_term(p1.y, t1.y, lam)
             + elem_term(p1.z, t1.z, lam) + elem_term(p1.w, t1.w, lam);
    }
    if (i < end) {
        float4 p = __ldcs(p4 + i);
        int4   t = __ldcs(y4 + i);
        acc += elem_term(p.x, t.x, lam) + elem_term(p.y, t.y, lam)
             + elem_term(p.z, t.z, lam) + elem_term(p.w, t.w, lam);
    }
    // scalar tail (n not divisible by 4) — handled by block 0
    if (blockIdx.x == 0) {
        for (int j = (nvec << 2) + threadIdx.x; j < n; j += bs)
            acc += elem_term(pred[j], y[j], lam);
    }

    // warp reduce
    #pragma unroll
    for (int off = 16; off > 0; off >>= 1)
        acc += __shfl_down_sync(0xFFFFFFFFu, acc, off);

    __shared__ float wsum[8];
    int lane = threadIdx.x & 31;
    int warp = threadIdx.x >> 5;
    if (lane == 0) wsum[warp] = acc;
    __syncthreads();

    __shared__ bool s_last;
    if (warp == 0) {
        float b = (lane < (bs >> 5)) ? wsum[lane] : 0.0f;
        #pragma unroll
        for (int off = 4; off > 0; off >>= 1)
            b += __shfl_down_sync(0xFFFFFFFFu, b, off);
        if (lane == 0) {
            atomicAdd(&g_acc, (double)b);
            __threadfence();
            unsigned prev = atomicAdd(&g_done, 1u);
            s_last = (prev == gridDim.x - 1);
        }
    }
    __syncthreads();

    // Last block to finish: publish result and reset state for next replay.
    if (s_last && threadIdx.x == 0) {
        double total = atomicAdd(&g_acc, 0.0);  // fenced read
        out[0] = (float)(total / (double)n);
        g_acc = 0.0;
        __threadfence();
        g_done = 0;
    }
}

extern "C" void kernel_launch(void* const* d_in, const int* in_sizes, int n_in,
                              void* d_out, int out_size) {
    const float* pred  = (const float*)d_in[0];
    const int*   y     = (const int*)d_in[1];
    const int*   lamda = (const int*)d_in[2];
    int n = in_sizes[0];

    const int threads = 256;
    int blocks = 148 * 8;  // one full wave at 8 CTAs/SM
    int nvec = (n >> 2) > 0 ? (n >> 2) : 1;
    int need = (nvec + threads - 1) / threads;
    if (blocks > need && need > 0) blocks = need;
    if (blocks < 1) blocks = 1;

    // Contiguous slice per block, rounded to a multiple of blockDim for
    // clean coalescing (last block takes the ragged end).
    int per_block = (nvec + blocks - 1) / blocks;
    per_block = ((per_block + threads - 1) / threads) * threads;

    sparse_loss_fused<<<blocks, threads>>>(pred, y, lamda, (float*)d_out, n, per_block);
}

// round 5
// speedup vs baseline: 1.0386x; 1.0386x over previous
#include <cuda_runtime.h>
#include <cuda_bf16.h>

#define EPSF 1e-10f

// Persistent scratch (no allocations allowed). Reset by the last block each
// run, so every graph replay starts from a clean state.
__device__ double g_acc = 0.0;
__device__ unsigned int g_done = 0;

__device__ __forceinline__ float elem_term(float p, int y, float lam) {
    // y==0 -> -log(1 - p + eps); else -> -lam * log(p + eps)
    bool neg = (y == 0);
    float arg   = neg ? (1.0f - p + EPSF) : (p + EPSF);
    float scale = neg ? 1.0f : lam;
    return -scale * __logf(arg);
}

__global__ void __launch_bounds__(256, 8)
sparse_loss_fused(const float* __restrict__ pred,
                  const int* __restrict__ y,
                  const int* __restrict__ lamda_raw,
                  float* __restrict__ out,
                  int n) {
    // Disambiguate lamda dtype: small non-negative int bit-pattern -> integer,
    // otherwise reinterpret bits as float. (int 5 and float 5.0f both -> 5.0f)
    int ibits = *lamda_raw;
    float lam = (ibits >= 0 && ibits < 1000000) ? (float)ibits : __int_as_float(ibits);

    int nvec = n >> 2;  // float4 count
    const float4* __restrict__ p4 = (const float4*)pred;
    const int4*   __restrict__ y4 = (const int4*)y;

    int tid    = blockIdx.x * blockDim.x + threadIdx.x;
    int stride = gridDim.x * blockDim.x;

    // Four independent accumulators: break the serial FADD dependency chain
    // so each loaded vector's math retires without waiting on the others.
    float a0 = 0.0f, a1 = 0.0f, a2 = 0.0f, a3 = 0.0f;

    // Grid-stride interleave (best measured distribution), 2-way batched:
    // 4 x LDG.128 front-batched per iteration, 32-bit indexing, <=32 regs.
    int i = tid;
    for (; i + stride < nvec; i += 2 * stride) {
        float4 p0 = __ldcs(p4 + i);
        float4 p1 = __ldcs(p4 + i + stride);
        int4   t0 = __ldcs(y4 + i);
        int4   t1 = __ldcs(y4 + i + stride);
        a0 += elem_term(p0.x, t0.x, lam) + elem_term(p1.x, t1.x, lam);
        a1 += elem_term(p0.y, t0.y, lam) + elem_term(p1.y, t1.y, lam);
        a2 += elem_term(p0.z, t0.z, lam) + elem_term(p1.z, t1.z, lam);
        a3 += elem_term(p0.w, t0.w, lam) + elem_term(p1.w, t1.w, lam);
    }
    if (i < nvec) {
        float4 p = __ldcs(p4 + i);
        int4   t = __ldcs(y4 + i);
        a0 += elem_term(p.x, t.x, lam);
        a1 += elem_term(p.y, t.y, lam);
        a2 += elem_term(p.z, t.z, lam);
        a3 += elem_term(p.w, t.w, lam);
    }
    // scalar tail (n not divisible by 4)
    for (int j = (nvec << 2) + tid; j < n; j += stride) {
        a0 += elem_term(pred[j], y[j], lam);
    }

    float acc = (a0 + a1) + (a2 + a3);

    // warp reduce
    #pragma unroll
    for (int off = 16; off > 0; off >>= 1)
        acc += __shfl_down_sync(0xFFFFFFFFu, acc, off);

    __shared__ float wsum[8];
    int lane = threadIdx.x & 31;
    int warp = threadIdx.x >> 5;
    if (lane == 0) wsum[warp] = acc;
    __syncthreads();

    __shared__ bool s_last;
    if (warp == 0) {
        float b = (lane < (blockDim.x >> 5)) ? wsum[lane] : 0.0f;
        #pragma unroll
        for (int off = 4; off > 0; off >>= 1)
            b += __shfl_down_sync(0xFFFFFFFFu, b, off);
        if (lane == 0) {
            atomicAdd(&g_acc, (double)b);
            __threadfence();
            unsigned prev = atomicAdd(&g_done, 1u);
            s_last = (prev == gridDim.x - 1);
        }
    }
    __syncthreads();

    // Last block to finish: publish result and reset state for next replay.
    if (s_last && threadIdx.x == 0) {
        double total = atomicAdd(&g_acc, 0.0);  // fenced read
        out[0] = (float)(total / (double)n);
        g_acc = 0.0;
        __threadfence();
        g_done = 0;
    }
}

extern "C" void kernel_launch(void* const* d_in, const int* in_sizes, int n_in,
                              void* d_out, int out_size) {
    const float* pred  = (const float*)d_in[0];
    const int*   y     = (const int*)d_in[1];
    const int*   lamda = (const int*)d_in[2];
    int n = in_sizes[0];

    const int threads = 256;
    int blocks = 148 * 8;  // one full wave at 8 CTAs/SM
    int nvec = (n >> 2) > 0 ? (n >> 2) : 1;
    int need = (nvec + threads - 1) / threads;
    if (blocks > need && need > 0) blocks = need;
    if (blocks < 1) blocks = 1;

    sparse_loss_fused<<<blocks, threads>>>(pred, y, lamda, (float*)d_out, n);
}

// round 8
// speedup vs baseline: 1.0835x; 1.0433x over previous
#include <cuda_runtime.h>
#include <cuda_bf16.h>

#define EPSF 1e-10f

// Persistent scratch (no allocations allowed). Reset by the last block each
// run, so every graph replay starts from a clean state.
__device__ double g_acc = 0.0;
__device__ unsigned int g_done = 0;

__device__ __forceinline__ float elem_term_acc(float p, int y, float neg_lam, float acc) {
    // y==0 -> -log(1 - p + eps); else -> -lam * log(p + eps)
    // One FADD (arg), one MUFU (log), one FFMA (scale+accumulate).
    bool neg = (y == 0);
    float arg = neg ? ((1.0f + EPSF) - p) : (p + EPSF);
    float m   = neg ? -1.0f : neg_lam;
    return fmaf(m, __logf(arg), acc);
}

__global__ void __launch_bounds__(256, 8)
sparse_loss_fused(const float* __restrict__ pred,
                  const int* __restrict__ y,
                  const int* __restrict__ lamda_raw,
                  float* __restrict__ out,
                  int n) {
    // Disambiguate lamda dtype: small non-negative int bit-pattern -> integer,
    // otherwise reinterpret bits as float. (int 5 and float 5.0f both -> 5.0f)
    int ibits = *lamda_raw;
    float lam = (ibits >= 0 && ibits < 1000000) ? (float)ibits : __int_as_float(ibits);
    float neg_lam = -lam;

    int nvec = n >> 2;  // float4 count
    const float4* __restrict__ p4 = (const float4*)pred;
    const int4*   __restrict__ y4 = (const int4*)y;

    int tid    = blockIdx.x * blockDim.x + threadIdx.x;
    int stride = gridDim.x * blockDim.x;

    // Four independent accumulators: no serial FADD chain across elements.
    float a0 = 0.0f, a1 = 0.0f, a2 = 0.0f, a3 = 0.0f;

    // Grid-stride interleave (best measured distribution), 2-way batched:
    // 4 x LDG.128 front-batched per iteration, 32-bit indexing, <=32 regs.
    int i = tid;
    for (; i + stride < nvec; i += 2 * stride) {
        float4 p0 = __ldcs(p4 + i);
        float4 p1 = __ldcs(p4 + i + stride);
        int4   t0 = __ldcs(y4 + i);
        int4   t1 = __ldcs(y4 + i + stride);
        a0 = elem_term_acc(p0.x, t0.x, neg_lam, a0);
        a1 = elem_term_acc(p0.y, t0.y, neg_lam, a1);
        a2 = elem_term_acc(p0.z, t0.z, neg_lam, a2);
        a3 = elem_term_acc(p0.w, t0.w, neg_lam, a3);
        a0 = elem_term_acc(p1.x, t1.x, neg_lam, a0);
        a1 = elem_term_acc(p1.y, t1.y, neg_lam, a1);
        a2 = elem_term_acc(p1.z, t1.z, neg_lam, a2);
        a3 = elem_term_acc(p1.w, t1.w, neg_lam, a3);
    }
    if (i < nvec) {
        float4 p = __ldcs(p4 + i);
        int4   t = __ldcs(y4 + i);
        a0 = elem_term_acc(p.x, t.x, neg_lam, a0);
        a1 = elem_term_acc(p.y, t.y, neg_lam, a1);
        a2 = elem_term_acc(p.z, t.z, neg_lam, a2);
        a3 = elem_term_acc(p.w, t.w, neg_lam, a3);
    }
    // scalar tail (n not divisible by 4)
    for (int j = (nvec << 2) + tid; j < n; j += stride) {
        a0 = elem_term_acc(pred[j], y[j], neg_lam, a0);
    }

    float acc = (a0 + a1) + (a2 + a3);

    // warp reduce
    #pragma unroll
    for (int off = 16; off > 0; off >>= 1)
        acc += __shfl_down_sync(0xFFFFFFFFu, acc, off);

    __shared__ float wsum[8];
    int lane = threadIdx.x & 31;
    int warp = threadIdx.x >> 5;
    if (lane == 0) wsum[warp] = acc;
    __syncthreads();

    __shared__ bool s_last;
    if (warp == 0) {
        float b = (lane < (blockDim.x >> 5)) ? wsum[lane] : 0.0f;
        #pragma unroll
        for (int off = 4; off > 0; off >>= 1)
            b += __shfl_down_sync(0xFFFFFFFFu, b, off);
        if (lane == 0) {
            atomicAdd(&g_acc, (double)b);
            __threadfence();
            unsigned prev = atomicAdd(&g_done, 1u);
            s_last = (prev == gridDim.x - 1);
        }
    }
    __syncthreads();

    // Last block to finish: publish result and reset state for next replay.
    if (s_last && threadIdx.x == 0) {
        double total = atomicAdd(&g_acc, 0.0);  // fenced read
        out[0] = (float)(total / (double)n);
        g_acc = 0.0;
        __threadfence();
        g_done = 0;
    }
}

extern "C" void kernel_launch(void* const* d_in, const int* in_sizes, int n_in,
                              void* d_out, int out_size) {
    const float* pred  = (const float*)d_in[0];
    const int*   y     = (const int*)d_in[1];
    const int*   lamda = (const int*)d_in[2];
    int n = in_sizes[0];

    const int threads = 256;
    int blocks = 148 * 8;  // one full wave at 8 CTAs/SM
    int nvec = (n >> 2) > 0 ? (n >> 2) : 1;
    int need = (nvec + threads - 1) / threads;
    if (blocks > need && need > 0) blocks = need;
    if (blocks < 1) blocks = 1;

    sparse_loss_fused<<<blocks, threads>>>(pred, y, lamda, (float*)d_out, n);
}